// round 1
// baseline (speedup 1.0000x reference)
#include <cuda_runtime.h>
#include <math.h>

// Problem constants
#define BB 2
#define SS 1024
#define DD 2048
#define HH 16
#define DHD 128
#define MM (BB * SS)   // 2048 rows

// ---------------------------------------------------------------------------
// Scratch: __device__ globals (allocation-free per harness rules)
// ---------------------------------------------------------------------------
__device__ float g_wq[DD * DD];
__device__ float g_wk[DD * DD];
__device__ float g_wv[DD * DD];
__device__ float g_wo[DD * DD];
__device__ float g_q[MM * DD];
__device__ float g_k[MM * DD];
__device__ float g_v[MM * DD];
__device__ float g_attn[MM * DD];

// ---------------------------------------------------------------------------
// Kernel 1: convert int8-valued int32 weights -> fp32, pre-scaled by the
// per-output-channel dequant scale. w is [out, in] row-major.
// ---------------------------------------------------------------------------
__global__ __launch_bounds__(256) void convert_w(const int* __restrict__ w,
                                                 const float* __restrict__ s,
                                                 float* __restrict__ out) {
    int i = (blockIdx.x * 256 + threadIdx.x) * 4;
    if (i >= DD * DD) return;
    int4 wv = *(const int4*)(w + i);
    float sc = s[i >> 11];  // row index = i / DD (DD = 2048), same row for all 4
    float4 o;
    o.x = (float)wv.x * sc;
    o.y = (float)wv.y * sc;
    o.z = (float)wv.z * sc;
    o.w = (float)wv.w * sc;
    *(float4*)(out + i) = o;
}

// ---------------------------------------------------------------------------
// Kernel 2: SGEMM  C[M,N] = A[M,K] * B[N,K]^T   (both K-major, M=N=K=2048)
// 128x128 block tile, BK=16, 256 threads, 8x8 per-thread microtile.
// ---------------------------------------------------------------------------
__global__ __launch_bounds__(256) void sgemm_nt(const float* __restrict__ A,
                                                const float* __restrict__ Bw,
                                                float* __restrict__ C) {
    __shared__ float As[16][132];  // [k][m], +4 pad
    __shared__ float Bs[16][132];  // [k][n]

    const int t  = threadIdx.x;
    const int bm = blockIdx.y * 128;
    const int bn = blockIdx.x * 128;
    const int tc = t & 15;         // 0..15 -> col block
    const int tr = t >> 4;         // 0..15 -> row block
    const int lr = t >> 2;         // 0..63 loader row
    const int lc = (t & 3) << 2;   // 0,4,8,12 loader k-offset

    float acc[8][8];
#pragma unroll
    for (int i = 0; i < 8; i++)
#pragma unroll
        for (int j = 0; j < 8; j++) acc[i][j] = 0.f;

    for (int k0 = 0; k0 < DD; k0 += 16) {
#pragma unroll
        for (int hh = 0; hh < 2; hh++) {
            int row = lr + hh * 64;
            float4 va = *(const float4*)(A + (size_t)(bm + row) * DD + k0 + lc);
            As[lc + 0][row] = va.x;
            As[lc + 1][row] = va.y;
            As[lc + 2][row] = va.z;
            As[lc + 3][row] = va.w;
            float4 vb = *(const float4*)(Bw + (size_t)(bn + row) * DD + k0 + lc);
            Bs[lc + 0][row] = vb.x;
            Bs[lc + 1][row] = vb.y;
            Bs[lc + 2][row] = vb.z;
            Bs[lc + 3][row] = vb.w;
        }
        __syncthreads();
#pragma unroll
        for (int kk = 0; kk < 16; kk++) {
            float ra[8], rb[8];
            *(float4*)(ra)     = *(const float4*)&As[kk][tr * 8];
            *(float4*)(ra + 4) = *(const float4*)&As[kk][tr * 8 + 4];
            *(float4*)(rb)     = *(const float4*)&Bs[kk][tc * 8];
            *(float4*)(rb + 4) = *(const float4*)&Bs[kk][tc * 8 + 4];
#pragma unroll
            for (int i = 0; i < 8; i++)
#pragma unroll
                for (int j = 0; j < 8; j++)
                    acc[i][j] = fmaf(ra[i], rb[j], acc[i][j]);
        }
        __syncthreads();
    }
#pragma unroll
    for (int i = 0; i < 8; i++) {
        float* cp = C + (size_t)(bm + tr * 8 + i) * DD + bn + tc * 8;
        *(float4*)cp       = make_float4(acc[i][0], acc[i][1], acc[i][2], acc[i][3]);
        *(float4*)(cp + 4) = make_float4(acc[i][4], acc[i][5], acc[i][6], acc[i][7]);
    }
}

// ---------------------------------------------------------------------------
// Kernel 3: fused RMSNorm (+weight) + rotate-half RoPE, in place on g_q / g_k.
// One block per (row, which). 256 threads.
// ---------------------------------------------------------------------------
__global__ __launch_bounds__(256) void norm_rope(const float* __restrict__ cosT,
                                                 const float* __restrict__ sinT,
                                                 const float* __restrict__ qn_w,
                                                 const float* __restrict__ kn_w) {
    float* x        = (blockIdx.y == 0) ? g_q : g_k;
    const float* w  = (blockIdx.y == 0) ? qn_w : kn_w;
    const int row   = blockIdx.x;       // 0..MM-1
    const int s     = row & (SS - 1);
    const int t     = threadIdx.x;

    __shared__ float buf[DD];
    __shared__ float red[8];

    float* xr = x + (size_t)row * DD;
    float ss = 0.f;
#pragma unroll
    for (int u = 0; u < 2; u++) {
        int i = (t + u * 256) * 4;
        float4 v = *(const float4*)(xr + i);
        *(float4*)(buf + i) = v;
        ss += v.x * v.x + v.y * v.y + v.z * v.z + v.w * v.w;
    }
#pragma unroll
    for (int off = 16; off; off >>= 1) ss += __shfl_xor_sync(0xffffffffu, ss, off);
    if ((t & 31) == 0) red[t >> 5] = ss;
    __syncthreads();
    float tot = 0.f;
#pragma unroll
    for (int wI = 0; wI < 8; wI++) tot += red[wI];
    const float inv = rsqrtf(tot * (1.0f / DD) + 1e-6f);

#pragma unroll
    for (int u = 0; u < 4; u++) {
        int p  = t + u * 256;           // 0..1023 rotation pairs
        int hh = p >> 6;                // head
        int i  = p & 63;                // in-half index
        int d1 = hh * DHD + i;
        int d2 = d1 + 64;
        float y1 = buf[d1] * inv * w[d1];
        float y2 = buf[d2] * inv * w[d2];
        float c1 = cosT[s * DHD + i],      s1 = sinT[s * DHD + i];
        float c2 = cosT[s * DHD + 64 + i], s2 = sinT[s * DHD + 64 + i];
        xr[d1] = y1 * c1 - y2 * s1;
        xr[d2] = y2 * c2 + y1 * s2;
    }
}

// ---------------------------------------------------------------------------
// Kernel 4: flash-attention (fp32). Block = (q-tile of 64, head, batch).
// Q/K staged K-major with a 16B-group XOR swizzle (conflict-free LDS.128 in
// the S loop, 2-way on the transpose store). Online softmax, P through smem.
// ---------------------------------------------------------------------------
__device__ __forceinline__ int sw(int d, int r) {
    // swizzled index into a [128][64] k-major tile (float units)
    return d * 64 + ((((r >> 2) ^ ((d >> 2) & 15))) << 2) + (r & 3);
}

#define FA_SMEM_FLOATS (128 * 64 + 128 * 64 + 64 * 128 + 64 * 68)
#define FA_SMEM_BYTES  (FA_SMEM_FLOATS * 4)

__global__ __launch_bounds__(256) void flash_attn(const int* __restrict__ lengths) {
    extern __shared__ float sm[];
    float* Qs = sm;                    // swizzled [d=128][r=64]
    float* Ks = Qs + 128 * 64;         // swizzled [d=128][r=64]
    float* Vs = Ks + 128 * 64;         // natural  [r=64][d=128]
    float* Ps = Vs + 64 * 128;         // [r=64][c=64], stride 68

    const int qt = blockIdx.x, h = blockIdx.y, b = blockIdx.z;
    const int t  = threadIdx.x;
    const int tc = t & 15, tr = t >> 4;
    const int len = lengths[b];
    const int s0  = qt * 64;

    const float* qbase = g_q + (size_t)(b * SS) * DD + h * DHD;
    const float* kbase = g_k + (size_t)(b * SS) * DD + h * DHD;
    const float* vbase = g_v + (size_t)(b * SS) * DD + h * DHD;

    // load Q tile (transposed + swizzled)
    for (int idx = t; idx < 64 * 32; idx += 256) {
        int r  = idx >> 5;
        int d4 = (idx & 31) << 2;
        float4 v = *(const float4*)(qbase + (size_t)(s0 + r) * DD + d4);
        Qs[sw(d4 + 0, r)] = v.x;
        Qs[sw(d4 + 1, r)] = v.y;
        Qs[sw(d4 + 2, r)] = v.z;
        Qs[sw(d4 + 3, r)] = v.w;
    }

    float m_[4], l_[4], o_[4][8];
#pragma unroll
    for (int i = 0; i < 4; i++) {
        m_[i] = -1e30f; l_[i] = 0.f;
#pragma unroll
        for (int j = 0; j < 8; j++) o_[i][j] = 0.f;
    }

    const int nkt = (len + 63) >> 6;
    const float scl = 0.08838834764831845f;  // 1/sqrt(128)

    for (int kt = 0; kt < nkt; kt++) {
        __syncthreads();  // prior PV done (and Q stores visible on iter 0)
        for (int idx = t; idx < 64 * 32; idx += 256) {
            int r  = idx >> 5;
            int d4 = (idx & 31) << 2;
            const float* kp = kbase + (size_t)(kt * 64 + r) * DD + d4;
            float4 kv = *(const float4*)kp;
            Ks[sw(d4 + 0, r)] = kv.x;
            Ks[sw(d4 + 1, r)] = kv.y;
            Ks[sw(d4 + 2, r)] = kv.z;
            Ks[sw(d4 + 3, r)] = kv.w;
            const float* vp = vbase + (size_t)(kt * 64 + r) * DD + d4;
            *(float4*)(Vs + r * 128 + d4) = *(const float4*)vp;
        }
        __syncthreads();

        // S = Q K^T  (each thread: rows tr*4..+3, cols tc*4..+3)
        float s4[4][4];
#pragma unroll
        for (int i = 0; i < 4; i++)
#pragma unroll
            for (int j = 0; j < 4; j++) s4[i][j] = 0.f;

#pragma unroll 8
        for (int kk = 0; kk < 128; kk++) {
            int swz = ((kk >> 2) & 15);
            float4 qa = *(const float4*)(Qs + kk * 64 + ((tr ^ swz) << 2));
            float4 ka = *(const float4*)(Ks + kk * 64 + ((tc ^ swz) << 2));
            float qv[4] = {qa.x, qa.y, qa.z, qa.w};
            float kv[4] = {ka.x, ka.y, ka.z, ka.w};
#pragma unroll
            for (int i = 0; i < 4; i++)
#pragma unroll
                for (int j = 0; j < 4; j++)
                    s4[i][j] = fmaf(qv[i], kv[j], s4[i][j]);
        }

        // scale + length mask
        const int cb = kt * 64 + tc * 4;
#pragma unroll
        for (int j = 0; j < 4; j++) {
            bool valid = (cb + j) < len;
#pragma unroll
            for (int i = 0; i < 4; i++)
                s4[i][j] = valid ? s4[i][j] * scl : -1e30f;
        }

        // online softmax
        float mn[4], alpha[4], rs[4];
#pragma unroll
        for (int i = 0; i < 4; i++) {
            float rm = fmaxf(fmaxf(s4[i][0], s4[i][1]), fmaxf(s4[i][2], s4[i][3]));
#pragma unroll
            for (int off = 1; off < 16; off <<= 1)
                rm = fmaxf(rm, __shfl_xor_sync(0xffffffffu, rm, off));
            mn[i]    = fmaxf(m_[i], rm);
            alpha[i] = __expf(m_[i] - mn[i]);
            float su = 0.f;
#pragma unroll
            for (int j = 0; j < 4; j++) {
                float p = __expf(s4[i][j] - mn[i]);
                s4[i][j] = p;
                su += p;
            }
#pragma unroll
            for (int off = 1; off < 16; off <<= 1)
                su += __shfl_xor_sync(0xffffffffu, su, off);
            rs[i] = su;
        }
#pragma unroll
        for (int i = 0; i < 4; i++) {
            l_[i] = l_[i] * alpha[i] + rs[i];
            m_[i] = mn[i];
#pragma unroll
            for (int j = 0; j < 8; j++) o_[i][j] *= alpha[i];
            *(float4*)(Ps + (tr * 4 + i) * 68 + tc * 4) =
                make_float4(s4[i][0], s4[i][1], s4[i][2], s4[i][3]);
        }
        __syncthreads();

        // O += P V   (each thread: rows tr*4..+3, cols tc*8..+7)
#pragma unroll 4
        for (int j = 0; j < 64; j++) {
            float4 v0 = *(const float4*)(Vs + j * 128 + tc * 8);
            float4 v1 = *(const float4*)(Vs + j * 128 + tc * 8 + 4);
#pragma unroll
            for (int i = 0; i < 4; i++) {
                float p = Ps[(tr * 4 + i) * 68 + j];
                o_[i][0] = fmaf(p, v0.x, o_[i][0]);
                o_[i][1] = fmaf(p, v0.y, o_[i][1]);
                o_[i][2] = fmaf(p, v0.z, o_[i][2]);
                o_[i][3] = fmaf(p, v0.w, o_[i][3]);
                o_[i][4] = fmaf(p, v1.x, o_[i][4]);
                o_[i][5] = fmaf(p, v1.y, o_[i][5]);
                o_[i][6] = fmaf(p, v1.z, o_[i][6]);
                o_[i][7] = fmaf(p, v1.w, o_[i][7]);
            }
        }
    }

    // epilogue: O / l -> g_attn[b, s0+r, h*128 + c]
    float* obase = g_attn + (size_t)(b * SS + s0) * DD + h * DHD;
#pragma unroll
    for (int i = 0; i < 4; i++) {
        float il = 1.f / l_[i];
        float* op = obase + (size_t)(tr * 4 + i) * DD + tc * 8;
        *(float4*)op       = make_float4(o_[i][0] * il, o_[i][1] * il,
                                         o_[i][2] * il, o_[i][3] * il);
        *(float4*)(op + 4) = make_float4(o_[i][4] * il, o_[i][5] * il,
                                         o_[i][6] * il, o_[i][7] * il);
    }
}

// ---------------------------------------------------------------------------
// Launch
// ---------------------------------------------------------------------------
extern "C" void kernel_launch(void* const* d_in, const int* in_sizes, int n_in,
                              void* d_out, int out_size) {
    const float* x     = (const float*)d_in[0];
    const float* wq_s  = (const float*)d_in[1];
    const float* wk_s  = (const float*)d_in[2];
    const float* wv_s  = (const float*)d_in[3];
    const float* wo_s  = (const float*)d_in[4];
    const float* qn_w  = (const float*)d_in[5];
    const float* kn_w  = (const float*)d_in[6];
    const float* cosT  = (const float*)d_in[7];
    const float* sinT  = (const float*)d_in[8];
    const int*   wq    = (const int*)d_in[9];
    const int*   wk    = (const int*)d_in[10];
    const int*   wv    = (const int*)d_in[11];
    const int*   wo    = (const int*)d_in[12];
    const int*   lens  = (const int*)d_in[13];
    float*       out   = (float*)d_out;

    float *pwq, *pwk, *pwv, *pwo, *pq, *pk, *pv, *pattn;
    cudaGetSymbolAddress((void**)&pwq, g_wq);
    cudaGetSymbolAddress((void**)&pwk, g_wk);
    cudaGetSymbolAddress((void**)&pwv, g_wv);
    cudaGetSymbolAddress((void**)&pwo, g_wo);
    cudaGetSymbolAddress((void**)&pq,  g_q);
    cudaGetSymbolAddress((void**)&pk,  g_k);
    cudaGetSymbolAddress((void**)&pv,  g_v);
    cudaGetSymbolAddress((void**)&pattn, g_attn);

    cudaFuncSetAttribute(flash_attn, cudaFuncAttributeMaxDynamicSharedMemorySize,
                         FA_SMEM_BYTES);

    const int cblocks = (DD * DD) / (256 * 4);
    convert_w<<<cblocks, 256>>>(wq, wq_s, pwq);
    convert_w<<<cblocks, 256>>>(wk, wk_s, pwk);
    convert_w<<<cblocks, 256>>>(wv, wv_s, pwv);
    convert_w<<<cblocks, 256>>>(wo, wo_s, pwo);

    dim3 ggrid(16, 16);
    sgemm_nt<<<ggrid, 256>>>(x, pwq, pq);
    sgemm_nt<<<ggrid, 256>>>(x, pwk, pk);
    sgemm_nt<<<ggrid, 256>>>(x, pwv, pv);

    norm_rope<<<dim3(MM, 2), 256>>>(cosT, sinT, qn_w, kn_w);

    flash_attn<<<dim3(SS / 64, HH, BB), 256, FA_SMEM_BYTES>>>(lens);

    sgemm_nt<<<ggrid, 256>>>(pattn, pwo, out);
}

// round 3
// speedup vs baseline: 2.4606x; 2.4606x over previous
#include <cuda_runtime.h>
#include <cuda_fp16.h>
#include <cstdint>
#include <stdint.h>
#include <math.h>

using u32 = unsigned int;

// Problem constants
#define BB 2
#define SS 1024
#define DD 2048
#define HH 16
#define DHD 128
#define MM (BB * SS)   // 2048 rows

// ---------------------------------------------------------------------------
// Scratch (__device__ globals; allocation-free per harness rules)
// ---------------------------------------------------------------------------
__device__ __half g_wq[DD * DD];
__device__ __half g_wk[DD * DD];
__device__ __half g_wv[DD * DD];
__device__ __half g_wo[DD * DD];
__device__ __half g_xh[MM * DD];      // hidden_states in fp16
__device__ __half g_attnh[MM * DD];   // attention output in fp16
__device__ float  g_q[MM * DD];
__device__ float  g_k[MM * DD];
__device__ float  g_v[MM * DD];

// ---------------------------------------------------------------------------
// Kernel 1a: int8-valued int32 weights -> fp16, pre-scaled by per-row scale.
// ---------------------------------------------------------------------------
__global__ __launch_bounds__(256) void convert_w(const int* __restrict__ w,
                                                 const float* __restrict__ s,
                                                 __half* __restrict__ out) {
    int i = (blockIdx.x * 256 + threadIdx.x) * 8;
    float sc = s[i >> 11];                 // row = i / 2048
    int4 a = *(const int4*)(w + i);
    int4 b = *(const int4*)(w + i + 4);
    __align__(16) __half h[8];
    h[0] = __float2half((float)a.x * sc);
    h[1] = __float2half((float)a.y * sc);
    h[2] = __float2half((float)a.z * sc);
    h[3] = __float2half((float)a.w * sc);
    h[4] = __float2half((float)b.x * sc);
    h[5] = __float2half((float)b.y * sc);
    h[6] = __float2half((float)b.z * sc);
    h[7] = __float2half((float)b.w * sc);
    *(uint4*)(out + i) = *(const uint4*)h;
}

// Kernel 1b: fp32 -> fp16
__global__ __launch_bounds__(256) void convert_x(const float* __restrict__ x,
                                                 __half* __restrict__ out) {
    int i = (blockIdx.x * 256 + threadIdx.x) * 8;
    float4 a = *(const float4*)(x + i);
    float4 b = *(const float4*)(x + i + 4);
    __align__(16) __half h[8];
    h[0] = __float2half(a.x); h[1] = __float2half(a.y);
    h[2] = __float2half(a.z); h[3] = __float2half(a.w);
    h[4] = __float2half(b.x); h[5] = __float2half(b.y);
    h[6] = __float2half(b.z); h[7] = __float2half(b.w);
    *(uint4*)(out + i) = *(const uint4*)h;
}

// ---------------------------------------------------------------------------
// Kernel 2: HGEMM via mma.sync.m16n8k16 (fp16 in, fp32 accum)
//   C[M,N] = A[M,K] * B[N,K]^T, M=N=K=2048, both A,B k-contiguous.
//   128x128 block tile, BK=32, 256 threads (8 warps, 2x4), warp tile 64x32.
// ---------------------------------------------------------------------------
#define WST 40   // smem row stride in halfs (80B -> conflict-free ldmatrix)

__device__ __forceinline__ uint4 ldsm_x4(u32 addr) {
    uint4 r;
    asm volatile("ldmatrix.sync.aligned.m8n8.x4.shared.b16 {%0,%1,%2,%3}, [%4];"
                 : "=r"(r.x), "=r"(r.y), "=r"(r.z), "=r"(r.w) : "r"(addr));
    return r;
}

__device__ __forceinline__ void mma16816(float* c, const uint4& a,
                                         u32 b0, u32 b1) {
    asm volatile(
        "mma.sync.aligned.m16n8k16.row.col.f32.f16.f16.f32 "
        "{%0,%1,%2,%3}, {%4,%5,%6,%7}, {%8,%9}, {%0,%1,%2,%3};"
        : "+f"(c[0]), "+f"(c[1]), "+f"(c[2]), "+f"(c[3])
        : "r"(a.x), "r"(a.y), "r"(a.z), "r"(a.w), "r"(b0), "r"(b1));
}

__global__ __launch_bounds__(256) void hgemm(const __half* __restrict__ A,
                                             const __half* __restrict__ B,
                                             float* __restrict__ C) {
    __shared__ __half As[128 * WST];
    __shared__ __half Bs[128 * WST];

    const int t    = threadIdx.x;
    const int bm   = blockIdx.y * 128;
    const int bn   = blockIdx.x * 128;
    const int warp = t >> 5, lane = t & 31;
    const int wm   = (warp & 1) * 64;      // warp row offset
    const int wn   = (warp >> 1) * 32;     // warp col offset
    const int lr   = lane & 7, g = lane >> 3;
    // A ldmatrix lane address: matrices (m0-7,k0-7),(m8-15,k0-7),(m0-7,k8-15),(m8-15,k8-15)
    const int arow = lr + (g & 1) * 8, acol = (g >> 1) * 8;
    // B ldmatrix lane address: (n0-7,k0-7),(n0-7,k8-15),(n8-15,k0-7),(n8-15,k8-15)
    const int brow = lr + (g >> 1) * 8, bcol = (g & 1) * 8;

    // loaders: each thread owns (row = t>>1, 16-half segment = (t&1)*16)
    const int ldrow = t >> 1, ldseg = (t & 1) * 16;
    const __half* Ag = A + (size_t)(bm + ldrow) * DD + ldseg;
    const __half* Bg = B + (size_t)(bn + ldrow) * DD + ldseg;
    __half* Asp = As + ldrow * WST + ldseg;
    __half* Bsp = Bs + ldrow * WST + ldseg;

    const u32 aAddr = (u32)__cvta_generic_to_shared(As + (wm + arow) * WST + acol);
    const u32 bAddr = (u32)__cvta_generic_to_shared(Bs + (wn + brow) * WST + bcol);

    float c[4][4][4];
#pragma unroll
    for (int mi = 0; mi < 4; mi++)
#pragma unroll
        for (int ni = 0; ni < 4; ni++)
#pragma unroll
            for (int e = 0; e < 4; e++) c[mi][ni][e] = 0.f;

    for (int k0 = 0; k0 < DD; k0 += 32) {
        uint4 va0 = *(const uint4*)(Ag + k0);
        uint4 va1 = *(const uint4*)(Ag + k0 + 8);
        uint4 vb0 = *(const uint4*)(Bg + k0);
        uint4 vb1 = *(const uint4*)(Bg + k0 + 8);
        __syncthreads();      // previous iteration's reads done
        *(uint4*)(Asp)     = va0;
        *(uint4*)(Asp + 8) = va1;
        *(uint4*)(Bsp)     = vb0;
        *(uint4*)(Bsp + 8) = vb1;
        __syncthreads();

#pragma unroll
        for (int ks = 0; ks < 32; ks += 16) {
            uint4 af[4], bf[2];
#pragma unroll
            for (int mi = 0; mi < 4; mi++)
                af[mi] = ldsm_x4(aAddr + (mi * 16 * WST + ks) * 2);
#pragma unroll
            for (int np = 0; np < 2; np++)
                bf[np] = ldsm_x4(bAddr + (np * 16 * WST + ks) * 2);
#pragma unroll
            for (int mi = 0; mi < 4; mi++)
#pragma unroll
                for (int np = 0; np < 2; np++) {
                    mma16816(c[mi][np * 2 + 0], af[mi], bf[np].x, bf[np].y);
                    mma16816(c[mi][np * 2 + 1], af[mi], bf[np].z, bf[np].w);
                }
        }
    }

    // epilogue: fragment rows l>>2 / +8, cols (l&3)*2
    const int r0 = bm + wm + (lane >> 2);
    const int cb = bn + wn + (lane & 3) * 2;
#pragma unroll
    for (int mi = 0; mi < 4; mi++)
#pragma unroll
        for (int ni = 0; ni < 4; ni++) {
            float* p0 = C + (size_t)(r0 + mi * 16) * DD + cb + ni * 8;
            float* p1 = p0 + 8 * DD;
            *(float2*)p0 = make_float2(c[mi][ni][0], c[mi][ni][1]);
            *(float2*)p1 = make_float2(c[mi][ni][2], c[mi][ni][3]);
        }
}

// ---------------------------------------------------------------------------
// Kernel 3: fused RMSNorm (+weight) + rotate-half RoPE, in place on g_q / g_k.
// ---------------------------------------------------------------------------
__global__ __launch_bounds__(256) void norm_rope(const float* __restrict__ cosT,
                                                 const float* __restrict__ sinT,
                                                 const float* __restrict__ qn_w,
                                                 const float* __restrict__ kn_w) {
    float* x       = (blockIdx.y == 0) ? g_q : g_k;
    const float* w = (blockIdx.y == 0) ? qn_w : kn_w;
    const int row  = blockIdx.x;
    const int s    = row & (SS - 1);
    const int t    = threadIdx.x;

    __shared__ float buf[DD];
    __shared__ float red[8];

    float* xr = x + (size_t)row * DD;
    float ss = 0.f;
#pragma unroll
    for (int u = 0; u < 2; u++) {
        int i = (t + u * 256) * 4;
        float4 v = *(const float4*)(xr + i);
        *(float4*)(buf + i) = v;
        ss += v.x * v.x + v.y * v.y + v.z * v.z + v.w * v.w;
    }
#pragma unroll
    for (int off = 16; off; off >>= 1) ss += __shfl_xor_sync(0xffffffffu, ss, off);
    if ((t & 31) == 0) red[t >> 5] = ss;
    __syncthreads();
    float tot = 0.f;
#pragma unroll
    for (int wI = 0; wI < 8; wI++) tot += red[wI];
    const float inv = rsqrtf(tot * (1.0f / DD) + 1e-6f);

#pragma unroll
    for (int u = 0; u < 4; u++) {
        int p  = t + u * 256;
        int hh = p >> 6;
        int i  = p & 63;
        int d1 = hh * DHD + i;
        int d2 = d1 + 64;
        float y1 = buf[d1] * inv * w[d1];
        float y2 = buf[d2] * inv * w[d2];
        float c1 = cosT[s * DHD + i],      s1 = sinT[s * DHD + i];
        float c2 = cosT[s * DHD + 64 + i], s2 = sinT[s * DHD + 64 + i];
        xr[d1] = y1 * c1 - y2 * s1;
        xr[d2] = y2 * c2 + y1 * s2;
    }
}

// ---------------------------------------------------------------------------
// Kernel 4: flash-attention (fp32), epilogue writes fp16 for the O-proj GEMM.
// ---------------------------------------------------------------------------
__device__ __forceinline__ int sw(int d, int r) {
    return d * 64 + ((((r >> 2) ^ ((d >> 2) & 15))) << 2) + (r & 3);
}

#define FA_SMEM_FLOATS (128 * 64 + 128 * 64 + 64 * 128 + 64 * 68)
#define FA_SMEM_BYTES  (FA_SMEM_FLOATS * 4)

__global__ __launch_bounds__(256) void flash_attn(const int* __restrict__ lengths) {
    extern __shared__ float sm[];
    float* Qs = sm;
    float* Ks = Qs + 128 * 64;
    float* Vs = Ks + 128 * 64;
    float* Ps = Vs + 64 * 128;

    const int qt = blockIdx.x, h = blockIdx.y, b = blockIdx.z;
    const int t  = threadIdx.x;
    const int tc = t & 15, tr = t >> 4;
    const int len = lengths[b];
    const int s0  = qt * 64;

    const float* qbase = g_q + (size_t)(b * SS) * DD + h * DHD;
    const float* kbase = g_k + (size_t)(b * SS) * DD + h * DHD;
    const float* vbase = g_v + (size_t)(b * SS) * DD + h * DHD;

    for (int idx = t; idx < 64 * 32; idx += 256) {
        int r  = idx >> 5;
        int d4 = (idx & 31) << 2;
        float4 v = *(const float4*)(qbase + (size_t)(s0 + r) * DD + d4);
        Qs[sw(d4 + 0, r)] = v.x;
        Qs[sw(d4 + 1, r)] = v.y;
        Qs[sw(d4 + 2, r)] = v.z;
        Qs[sw(d4 + 3, r)] = v.w;
    }

    float m_[4], l_[4], o_[4][8];
#pragma unroll
    for (int i = 0; i < 4; i++) {
        m_[i] = -1e30f; l_[i] = 0.f;
#pragma unroll
        for (int j = 0; j < 8; j++) o_[i][j] = 0.f;
    }

    const int nkt = (len + 63) >> 6;
    const float scl = 0.08838834764831845f;

    for (int kt = 0; kt < nkt; kt++) {
        __syncthreads();
        for (int idx = t; idx < 64 * 32; idx += 256) {
            int r  = idx >> 5;
            int d4 = (idx & 31) << 2;
            const float* kp = kbase + (size_t)(kt * 64 + r) * DD + d4;
            float4 kv = *(const float4*)kp;
            Ks[sw(d4 + 0, r)] = kv.x;
            Ks[sw(d4 + 1, r)] = kv.y;
            Ks[sw(d4 + 2, r)] = kv.z;
            Ks[sw(d4 + 3, r)] = kv.w;
            const float* vp = vbase + (size_t)(kt * 64 + r) * DD + d4;
            *(float4*)(Vs + r * 128 + d4) = *(const float4*)vp;
        }
        __syncthreads();

        float s4[4][4];
#pragma unroll
        for (int i = 0; i < 4; i++)
#pragma unroll
            for (int j = 0; j < 4; j++) s4[i][j] = 0.f;

#pragma unroll 8
        for (int kk = 0; kk < 128; kk++) {
            int swz = ((kk >> 2) & 15);
            float4 qa = *(const float4*)(Qs + kk * 64 + ((tr ^ swz) << 2));
            float4 ka = *(const float4*)(Ks + kk * 64 + ((tc ^ swz) << 2));
            float qv[4] = {qa.x, qa.y, qa.z, qa.w};
            float kv[4] = {ka.x, ka.y, ka.z, ka.w};
#pragma unroll
            for (int i = 0; i < 4; i++)
#pragma unroll
                for (int j = 0; j < 4; j++)
                    s4[i][j] = fmaf(qv[i], kv[j], s4[i][j]);
        }

        const int cb = kt * 64 + tc * 4;
#pragma unroll
        for (int j = 0; j < 4; j++) {
            bool valid = (cb + j) < len;
#pragma unroll
            for (int i = 0; i < 4; i++)
                s4[i][j] = valid ? s4[i][j] * scl : -1e30f;
        }

        float mn[4], alpha[4], rs[4];
#pragma unroll
        for (int i = 0; i < 4; i++) {
            float rm = fmaxf(fmaxf(s4[i][0], s4[i][1]), fmaxf(s4[i][2], s4[i][3]));
#pragma unroll
            for (int off = 1; off < 16; off <<= 1)
                rm = fmaxf(rm, __shfl_xor_sync(0xffffffffu, rm, off));
            mn[i]    = fmaxf(m_[i], rm);
            alpha[i] = __expf(m_[i] - mn[i]);
            float su = 0.f;
#pragma unroll
            for (int j = 0; j < 4; j++) {
                float p = __expf(s4[i][j] - mn[i]);
                s4[i][j] = p;
                su += p;
            }
#pragma unroll
            for (int off = 1; off < 16; off <<= 1)
                su += __shfl_xor_sync(0xffffffffu, su, off);
            rs[i] = su;
        }
#pragma unroll
        for (int i = 0; i < 4; i++) {
            l_[i] = l_[i] * alpha[i] + rs[i];
            m_[i] = mn[i];
#pragma unroll
            for (int j = 0; j < 8; j++) o_[i][j] *= alpha[i];
            *(float4*)(Ps + (tr * 4 + i) * 68 + tc * 4) =
                make_float4(s4[i][0], s4[i][1], s4[i][2], s4[i][3]);
        }
        __syncthreads();

#pragma unroll 4
        for (int j = 0; j < 64; j++) {
            float4 v0 = *(const float4*)(Vs + j * 128 + tc * 8);
            float4 v1 = *(const float4*)(Vs + j * 128 + tc * 8 + 4);
#pragma unroll
            for (int i = 0; i < 4; i++) {
                float p = Ps[(tr * 4 + i) * 68 + j];
                o_[i][0] = fmaf(p, v0.x, o_[i][0]);
                o_[i][1] = fmaf(p, v0.y, o_[i][1]);
                o_[i][2] = fmaf(p, v0.z, o_[i][2]);
                o_[i][3] = fmaf(p, v0.w, o_[i][3]);
                o_[i][4] = fmaf(p, v1.x, o_[i][4]);
                o_[i][5] = fmaf(p, v1.y, o_[i][5]);
                o_[i][6] = fmaf(p, v1.z, o_[i][6]);
                o_[i][7] = fmaf(p, v1.w, o_[i][7]);
            }
        }
    }

    // epilogue -> fp16 g_attnh[b, s0+r, h*128 + c]
    __half* obase = g_attnh + (size_t)(b * SS + s0) * DD + h * DHD;
#pragma unroll
    for (int i = 0; i < 4; i++) {
        float il = 1.f / l_[i];
        __half* op = obase + (size_t)(tr * 4 + i) * DD + tc * 8;
        __align__(16) __half hv[8];
#pragma unroll
        for (int j = 0; j < 8; j++) hv[j] = __float2half(o_[i][j] * il);
        *(uint4*)op = *(const uint4*)hv;
    }
}

// ---------------------------------------------------------------------------
// Launch
// ---------------------------------------------------------------------------
extern "C" void kernel_launch(void* const* d_in, const int* in_sizes, int n_in,
                              void* d_out, int out_size) {
    const float* x     = (const float*)d_in[0];
    const float* wq_s  = (const float*)d_in[1];
    const float* wk_s  = (const float*)d_in[2];
    const float* wv_s  = (const float*)d_in[3];
    const float* wo_s  = (const float*)d_in[4];
    const float* qn_w  = (const float*)d_in[5];
    const float* kn_w  = (const float*)d_in[6];
    const float* cosT  = (const float*)d_in[7];
    const float* sinT  = (const float*)d_in[8];
    const int*   wq    = (const int*)d_in[9];
    const int*   wk    = (const int*)d_in[10];
    const int*   wv    = (const int*)d_in[11];
    const int*   wo    = (const int*)d_in[12];
    const int*   lens  = (const int*)d_in[13];
    float*       out   = (float*)d_out;

    __half *pwq, *pwk, *pwv, *pwo, *pxh, *pattnh;
    float *pq, *pk, *pv;
    cudaGetSymbolAddress((void**)&pwq, g_wq);
    cudaGetSymbolAddress((void**)&pwk, g_wk);
    cudaGetSymbolAddress((void**)&pwv, g_wv);
    cudaGetSymbolAddress((void**)&pwo, g_wo);
    cudaGetSymbolAddress((void**)&pxh, g_xh);
    cudaGetSymbolAddress((void**)&pattnh, g_attnh);
    cudaGetSymbolAddress((void**)&pq, g_q);
    cudaGetSymbolAddress((void**)&pk, g_k);
    cudaGetSymbolAddress((void**)&pv, g_v);

    cudaFuncSetAttribute(flash_attn, cudaFuncAttributeMaxDynamicSharedMemorySize,
                         FA_SMEM_BYTES);

    const int cblocks = (DD * DD) / (256 * 8);
    convert_w<<<cblocks, 256>>>(wq, wq_s, pwq);
    convert_w<<<cblocks, 256>>>(wk, wk_s, pwk);
    convert_w<<<cblocks, 256>>>(wv, wv_s, pwv);
    convert_w<<<cblocks, 256>>>(wo, wo_s, pwo);
    convert_x<<<(MM * DD) / (256 * 8), 256>>>(x, pxh);

    dim3 ggrid(16, 16);
    hgemm<<<ggrid, 256>>>(pxh, pwq, pq);
    hgemm<<<ggrid, 256>>>(pxh, pwk, pk);
    hgemm<<<ggrid, 256>>>(pxh, pwv, pv);

    norm_rope<<<dim3(MM, 2), 256>>>(cosT, sinT, qn_w, kn_w);

    flash_attn<<<dim3(SS / 64, HH, BB), 256, FA_SMEM_BYTES>>>(lens);

    hgemm<<<ggrid, 256>>>(pattnh, pwo, out);
}

// round 4
// speedup vs baseline: 6.6879x; 2.7179x over previous
#include <cuda_runtime.h>
#include <cuda_fp16.h>
#include <cstdint>
#include <stdint.h>
#include <math.h>

using u32 = unsigned int;

// Problem constants
#define BB 2
#define SS 1024
#define DD 2048
#define HH 16
#define DHD 128
#define MM (BB * SS)   // 2048 rows

// ---------------------------------------------------------------------------
// Scratch (__device__ globals; allocation-free per harness rules)
// ---------------------------------------------------------------------------
__device__ __half g_wq[DD * DD];
__device__ __half g_wk[DD * DD];
__device__ __half g_wv[DD * DD];
__device__ __half g_wo[DD * DD];
__device__ __half g_xh[MM * DD];      // hidden_states fp16
__device__ __half g_attnh[MM * DD];   // attention output fp16
__device__ float  g_q[MM * DD];       // Q pre-norm (fp32)
__device__ float  g_k[MM * DD];       // K pre-norm (fp32)
__device__ __half g_qh[MM * DD];      // Q post norm+rope (fp16)
__device__ __half g_kh[MM * DD];      // K post norm+rope (fp16)
__device__ __half g_vh[MM * DD];      // V (fp16)

// ---------------------------------------------------------------------------
// PTX helpers
// ---------------------------------------------------------------------------
__device__ __forceinline__ uint4 ldsm_x4(u32 addr) {
    uint4 r;
    asm volatile("ldmatrix.sync.aligned.m8n8.x4.shared.b16 {%0,%1,%2,%3}, [%4];"
                 : "=r"(r.x), "=r"(r.y), "=r"(r.z), "=r"(r.w) : "r"(addr));
    return r;
}
__device__ __forceinline__ uint4 ldsm_x4_t(u32 addr) {
    uint4 r;
    asm volatile("ldmatrix.sync.aligned.m8n8.x4.trans.shared.b16 {%0,%1,%2,%3}, [%4];"
                 : "=r"(r.x), "=r"(r.y), "=r"(r.z), "=r"(r.w) : "r"(addr));
    return r;
}
__device__ __forceinline__ void mma16816(float* c, const uint4& a, u32 b0, u32 b1) {
    asm volatile(
        "mma.sync.aligned.m16n8k16.row.col.f32.f16.f16.f32 "
        "{%0,%1,%2,%3}, {%4,%5,%6,%7}, {%8,%9}, {%0,%1,%2,%3};"
        : "+f"(c[0]), "+f"(c[1]), "+f"(c[2]), "+f"(c[3])
        : "r"(a.x), "r"(a.y), "r"(a.z), "r"(a.w), "r"(b0), "r"(b1));
}
__device__ __forceinline__ void cp16(u32 dst, const void* src) {
    asm volatile("cp.async.cg.shared.global [%0], [%1], 16;" :: "r"(dst), "l"(src));
}
#define CP_COMMIT() asm volatile("cp.async.commit_group;")
#define CP_WAIT(N)  asm volatile("cp.async.wait_group %0;" :: "n"(N))

__device__ __forceinline__ u32 h2u(float a, float b) {
    __half2 h = __floats2half2_rn(a, b);
    return *reinterpret_cast<u32*>(&h);
}

// ---------------------------------------------------------------------------
// Kernel 1a: int8-valued int32 weights -> fp16, pre-scaled by per-row scale.
// ---------------------------------------------------------------------------
__global__ __launch_bounds__(256) void convert_w(const int* __restrict__ w,
                                                 const float* __restrict__ s,
                                                 __half* __restrict__ out) {
    int i = (blockIdx.x * 256 + threadIdx.x) * 8;
    float sc = s[i >> 11];
    int4 a = *(const int4*)(w + i);
    int4 b = *(const int4*)(w + i + 4);
    __align__(16) __half h[8];
    h[0] = __float2half((float)a.x * sc);
    h[1] = __float2half((float)a.y * sc);
    h[2] = __float2half((float)a.z * sc);
    h[3] = __float2half((float)a.w * sc);
    h[4] = __float2half((float)b.x * sc);
    h[5] = __float2half((float)b.y * sc);
    h[6] = __float2half((float)b.z * sc);
    h[7] = __float2half((float)b.w * sc);
    *(uint4*)(out + i) = *(const uint4*)h;
}

__global__ __launch_bounds__(256) void convert_x(const float* __restrict__ x,
                                                 __half* __restrict__ out) {
    int i = (blockIdx.x * 256 + threadIdx.x) * 8;
    float4 a = *(const float4*)(x + i);
    float4 b = *(const float4*)(x + i + 4);
    __align__(16) __half h[8];
    h[0] = __float2half(a.x); h[1] = __float2half(a.y);
    h[2] = __float2half(a.z); h[3] = __float2half(a.w);
    h[4] = __float2half(b.x); h[5] = __float2half(b.y);
    h[6] = __float2half(b.z); h[7] = __float2half(b.w);
    *(uint4*)(out + i) = *(const uint4*)h;
}

// ---------------------------------------------------------------------------
// Kernel 2: HGEMM, 128x128 tile, BK=64, 3-stage cp.async pipeline.
//   C[M,N] = A[M,K]*B[N,K]^T. 256 threads, warp tile 64x32.
// ---------------------------------------------------------------------------
#define HG_STG 9216                       // halfs per matrix per stage (128*72)
#define HG_STAGE_BYTES (2 * HG_STG * 2)   // A+B, 36864 B
#define HG_BYTES (3 * HG_STAGE_BYTES)     // 110592 B

template <typename OutT>
__device__ __forceinline__ void store2(OutT* p, float a, float b);
template <> __device__ __forceinline__ void store2<float>(float* p, float a, float b) {
    *(float2*)p = make_float2(a, b);
}
template <> __device__ __forceinline__ void store2<__half>(__half* p, float a, float b) {
    *(__half2*)p = __floats2half2_rn(a, b);
}

template <typename OutT>
__global__ __launch_bounds__(256, 2) void hgemm(const __half* __restrict__ A,
                                                const __half* __restrict__ B,
                                                OutT* __restrict__ C) {
    extern __shared__ __half hsm[];
    const u32 smb = (u32)__cvta_generic_to_shared(hsm);

    const int t = threadIdx.x, warp = t >> 5, lane = t & 31;
    const int bm = blockIdx.y * 128, bn = blockIdx.x * 128;
    const int wm = (warp & 1) * 64, wn = (warp >> 1) * 32;
    const int lr = lane & 7, g = lane >> 3;
    const u32 aOff = (u32)(((wm + lr + (g & 1) * 8) * 72 + (g >> 1) * 8) * 2);
    const u32 bOff = (u32)(((wn + lr + (g >> 1) * 8) * 72 + (g & 1) * 8) * 2);

    float c[4][4][4];
#pragma unroll
    for (int mi = 0; mi < 4; mi++)
#pragma unroll
        for (int ni = 0; ni < 4; ni++)
#pragma unroll
            for (int e = 0; e < 4; e++) c[mi][ni][e] = 0.f;

    auto load_stage = [&](int st, int k0) {
        u32 sb = smb + (u32)(st * HG_STAGE_BYTES);
#pragma unroll
        for (int i = 0; i < 4; i++) {
            int id = t + 256 * i;
            int r = id >> 3, cc = id & 7;
            cp16(sb + (u32)((r * 72 + cc * 8) * 2),
                 A + (size_t)(bm + r) * DD + k0 + cc * 8);
            cp16(sb + (u32)(HG_STG * 2) + (u32)((r * 72 + cc * 8) * 2),
                 B + (size_t)(bn + r) * DD + k0 + cc * 8);
        }
    };

    load_stage(0, 0);  CP_COMMIT();
    load_stage(1, 64); CP_COMMIT();

    for (int kt = 0; kt < 32; kt++) {
        if (kt < 31) { CP_WAIT(1); } else { CP_WAIT(0); }
        __syncthreads();
        if (kt + 2 < 32) { load_stage((kt + 2) % 3, (kt + 2) * 64); CP_COMMIT(); }

        u32 ab = smb + (u32)((kt % 3) * HG_STAGE_BYTES) + aOff;
        u32 bb = smb + (u32)((kt % 3) * HG_STAGE_BYTES + HG_STG * 2) + bOff;
#pragma unroll
        for (int ks = 0; ks < 64; ks += 16) {
            uint4 af[4], bf[2];
#pragma unroll
            for (int mi = 0; mi < 4; mi++)
                af[mi] = ldsm_x4(ab + (u32)((mi * 16 * 72 + ks) * 2));
#pragma unroll
            for (int np = 0; np < 2; np++)
                bf[np] = ldsm_x4(bb + (u32)((np * 16 * 72 + ks) * 2));
#pragma unroll
            for (int mi = 0; mi < 4; mi++)
#pragma unroll
                for (int np = 0; np < 2; np++) {
                    mma16816(c[mi][np * 2 + 0], af[mi], bf[np].x, bf[np].y);
                    mma16816(c[mi][np * 2 + 1], af[mi], bf[np].z, bf[np].w);
                }
        }
    }

    const int r0 = bm + wm + (lane >> 2);
    const int cb = bn + wn + (lane & 3) * 2;
#pragma unroll
    for (int mi = 0; mi < 4; mi++)
#pragma unroll
        for (int ni = 0; ni < 4; ni++) {
            int row = r0 + mi * 16, col = cb + ni * 8;
            store2<OutT>(C + (size_t)row * DD + col, c[mi][ni][0], c[mi][ni][1]);
            store2<OutT>(C + (size_t)(row + 8) * DD + col, c[mi][ni][2], c[mi][ni][3]);
        }
}

// ---------------------------------------------------------------------------
// Kernel 3: RMSNorm + RoPE; fp32 in (g_q/g_k), fp16 out (g_qh/g_kh).
// ---------------------------------------------------------------------------
__global__ __launch_bounds__(256) void norm_rope(const float* __restrict__ cosT,
                                                 const float* __restrict__ sinT,
                                                 const float* __restrict__ qn_w,
                                                 const float* __restrict__ kn_w) {
    const float* x  = (blockIdx.y == 0) ? g_q : g_k;
    __half* xo      = (blockIdx.y == 0) ? g_qh : g_kh;
    const float* w  = (blockIdx.y == 0) ? qn_w : kn_w;
    const int row = blockIdx.x;
    const int s   = row & (SS - 1);
    const int t   = threadIdx.x;

    __shared__ float buf[DD];
    __shared__ float red[8];

    const float* xr = x + (size_t)row * DD;
    float ss = 0.f;
#pragma unroll
    for (int u = 0; u < 2; u++) {
        int i = (t + u * 256) * 4;
        float4 v = *(const float4*)(xr + i);
        *(float4*)(buf + i) = v;
        ss += v.x * v.x + v.y * v.y + v.z * v.z + v.w * v.w;
    }
#pragma unroll
    for (int off = 16; off; off >>= 1) ss += __shfl_xor_sync(0xffffffffu, ss, off);
    if ((t & 31) == 0) red[t >> 5] = ss;
    __syncthreads();
    float tot = 0.f;
#pragma unroll
    for (int wI = 0; wI < 8; wI++) tot += red[wI];
    const float inv = rsqrtf(tot * (1.0f / DD) + 1e-6f);

    __half* xor_ = xo + (size_t)row * DD;
#pragma unroll
    for (int u = 0; u < 4; u++) {
        int p  = t + u * 256;
        int hh = p >> 6;
        int i  = p & 63;
        int d1 = hh * DHD + i;
        int d2 = d1 + 64;
        float y1 = buf[d1] * inv * w[d1];
        float y2 = buf[d2] * inv * w[d2];
        float c1 = cosT[s * DHD + i],      s1 = sinT[s * DHD + i];
        float c2 = cosT[s * DHD + 64 + i], s2 = sinT[s * DHD + 64 + i];
        xor_[d1] = __float2half(y1 * c1 - y2 * s1);
        xor_[d2] = __float2half(y2 * c2 + y1 * s2);
    }
}

// ---------------------------------------------------------------------------
// Kernel 4: flash-attention with mma.m16n8k16, fp16 QKV, fp32 softmax state.
//   Block = (64 q-rows, head, batch), 128 threads (4 warps, 16 q-rows each).
//   Smem tiles [64 rows][128 halfs], 16B-chunk XOR swizzle; 3-stage cp.async
//   pipeline on K/V.
// ---------------------------------------------------------------------------
#define FA_Q_HALFS (64 * 128)
#define FA_KV_HALFS (64 * 128)
#define FA_STAGE_HALFS (2 * FA_KV_HALFS)
#define FA_BYTES ((FA_Q_HALFS + 3 * FA_STAGE_HALFS) * 2)   // 114688

__device__ __forceinline__ void fa_load_kv(u32 smb, int st, const __half* kg,
                                           const __half* vg, int kt, int t) {
    u32 kb = smb + (u32)((FA_Q_HALFS + st * FA_STAGE_HALFS) * 2);
    u32 vb = kb + (u32)(FA_KV_HALFS * 2);
#pragma unroll
    for (int i = 0; i < 8; i++) {
        int id = t + 128 * i;
        int r = id >> 4, cc = id & 15;
        u32 off = (u32)(((r * 128) + ((cc ^ (r & 7)) << 3)) << 1);
        cp16(kb + off, kg + (size_t)(kt * 64 + r) * DD + cc * 8);
        cp16(vb + off, vg + (size_t)(kt * 64 + r) * DD + cc * 8);
    }
}

__global__ __launch_bounds__(128) void flash_attn(const int* __restrict__ lengths) {
    extern __shared__ __half fsm[];
    const u32 smb = (u32)__cvta_generic_to_shared(fsm);

    const int qt = blockIdx.x, h = blockIdx.y, b = blockIdx.z;
    const int t = threadIdx.x, warp = t >> 5, lane = t & 31;
    const int lr = lane & 7, g = lane >> 3;
    const int len = lengths[b];
    const int s0  = qt * 64;
    const int nkt = (len + 63) >> 6;

    const __half* qg = g_qh + (size_t)(b * SS) * DD + h * DHD;
    const __half* kg = g_kh + (size_t)(b * SS) * DD + h * DHD;
    const __half* vg = g_vh + (size_t)(b * SS) * DD + h * DHD;

    // group0: Q tile + KV tile 0
#pragma unroll
    for (int i = 0; i < 8; i++) {
        int id = t + 128 * i;
        int r = id >> 4, cc = id & 15;
        u32 off = (u32)(((r * 128) + ((cc ^ (r & 7)) << 3)) << 1);
        cp16(smb + off, qg + (size_t)(s0 + r) * DD + cc * 8);
    }
    fa_load_kv(smb, 0, kg, vg, 0, t);
    CP_COMMIT();
    if (nkt > 1) { fa_load_kv(smb, 1, kg, vg, 1, t); CP_COMMIT(); }

    // lane constants
    const int qrow = 16 * warp + lr + (g & 1) * 8, qx = qrow & 7;
    const int krow = lr + (g >> 1) * 8, kcol = g & 1, kx = krow & 7;
    const int vrow = lr + (g & 1) * 8, vcol = g >> 1, vx = vrow & 7;

    uint4 qf[8];
    float o[16][4];
#pragma unroll
    for (int j2 = 0; j2 < 16; j2++)
#pragma unroll
        for (int e = 0; e < 4; e++) o[j2][e] = 0.f;
    float m0 = -1e30f, m1 = -1e30f, l0 = 0.f, l1 = 0.f;
    const float scl = 0.08838834764831845f;   // 1/sqrt(128)

    for (int kt = 0; kt < nkt; kt++) {
        if (kt < nkt - 1) { CP_WAIT(1); } else { CP_WAIT(0); }
        __syncthreads();
        if (kt == 0) {
#pragma unroll
            for (int ks = 0; ks < 8; ks++)
                qf[ks] = ldsm_x4(smb + (u32)(((qrow * 128) +
                                  (((2 * ks + (g >> 1)) ^ qx) << 3)) << 1));
        }
        if (kt + 2 < nkt) { fa_load_kv(smb, (kt + 2) % 3, kg, vg, kt + 2, t); CP_COMMIT(); }

        const u32 kbase = smb + (u32)((FA_Q_HALFS + (kt % 3) * FA_STAGE_HALFS) * 2);
        const u32 vbase = kbase + (u32)(FA_KV_HALFS * 2);

        // ---- S = Q K^T ----
        float s[8][4];
#pragma unroll
        for (int j = 0; j < 8; j++)
#pragma unroll
            for (int e = 0; e < 4; e++) s[j][e] = 0.f;

#pragma unroll
        for (int ks = 0; ks < 8; ks++) {
#pragma unroll
            for (int np = 0; np < 4; np++) {
                uint4 bf = ldsm_x4(kbase + (u32)((((16 * np + krow) * 128) +
                                    (((2 * ks + kcol) ^ kx) << 3)) << 1));
                mma16816(s[2 * np],     qf[ks], bf.x, bf.y);
                mma16816(s[2 * np + 1], qf[ks], bf.z, bf.w);
            }
        }

        // ---- mask + online softmax ----
        const int cb = kt * 64 + 2 * (lane & 3);
        float mx0 = -1e30f, mx1 = -1e30f;
#pragma unroll
        for (int j = 0; j < 8; j++) {
            int c0 = cb + 8 * j;
            s[j][0] = (c0 < len)     ? s[j][0] * scl : -1e30f;
            s[j][1] = (c0 + 1 < len) ? s[j][1] * scl : -1e30f;
            s[j][2] = (c0 < len)     ? s[j][2] * scl : -1e30f;
            s[j][3] = (c0 + 1 < len) ? s[j][3] * scl : -1e30f;
            mx0 = fmaxf(mx0, fmaxf(s[j][0], s[j][1]));
            mx1 = fmaxf(mx1, fmaxf(s[j][2], s[j][3]));
        }
        mx0 = fmaxf(mx0, __shfl_xor_sync(0xffffffffu, mx0, 1));
        mx0 = fmaxf(mx0, __shfl_xor_sync(0xffffffffu, mx0, 2));
        mx1 = fmaxf(mx1, __shfl_xor_sync(0xffffffffu, mx1, 1));
        mx1 = fmaxf(mx1, __shfl_xor_sync(0xffffffffu, mx1, 2));

        float mn0 = fmaxf(m0, mx0), mn1 = fmaxf(m1, mx1);
        float al0 = __expf(m0 - mn0), al1 = __expf(m1 - mn1);
        float sum0 = 0.f, sum1 = 0.f;
        u32 pf[8][2];
#pragma unroll
        for (int j = 0; j < 8; j++) {
            float p0 = __expf(s[j][0] - mn0), p1 = __expf(s[j][1] - mn0);
            float p2 = __expf(s[j][2] - mn1), p3 = __expf(s[j][3] - mn1);
            sum0 += p0 + p1; sum1 += p2 + p3;
            pf[j][0] = h2u(p0, p1);
            pf[j][1] = h2u(p2, p3);
        }
        sum0 += __shfl_xor_sync(0xffffffffu, sum0, 1);
        sum0 += __shfl_xor_sync(0xffffffffu, sum0, 2);
        sum1 += __shfl_xor_sync(0xffffffffu, sum1, 1);
        sum1 += __shfl_xor_sync(0xffffffffu, sum1, 2);
        l0 = l0 * al0 + sum0; l1 = l1 * al1 + sum1;
        m0 = mn0; m1 = mn1;
#pragma unroll
        for (int j2 = 0; j2 < 16; j2++) {
            o[j2][0] *= al0; o[j2][1] *= al0;
            o[j2][2] *= al1; o[j2][3] *= al1;
        }

        // ---- O += P V ----
#pragma unroll
        for (int k2 = 0; k2 < 4; k2++) {
            uint4 a;
            a.x = pf[2 * k2][0];     a.y = pf[2 * k2][1];
            a.z = pf[2 * k2 + 1][0]; a.w = pf[2 * k2 + 1][1];
#pragma unroll
            for (int np = 0; np < 8; np++) {
                uint4 bf = ldsm_x4_t(vbase + (u32)((((16 * k2 + vrow) * 128) +
                                     (((2 * np + vcol) ^ vx) << 3)) << 1));
                mma16816(o[2 * np],     a, bf.x, bf.y);
                mma16816(o[2 * np + 1], a, bf.z, bf.w);
            }
        }
    }

    // ---- epilogue ----
    const float il0 = 1.f / l0, il1 = 1.f / l1;
    const int r0 = s0 + 16 * warp + (lane >> 2);
    __half* ob = g_attnh + (size_t)(b * SS) * DD + h * DHD;
#pragma unroll
    for (int j2 = 0; j2 < 16; j2++) {
        int col = 8 * j2 + 2 * (lane & 3);
        *(__half2*)(ob + (size_t)r0 * DD + col) =
            __floats2half2_rn(o[j2][0] * il0, o[j2][1] * il0);
        *(__half2*)(ob + (size_t)(r0 + 8) * DD + col) =
            __floats2half2_rn(o[j2][2] * il1, o[j2][3] * il1);
    }
}

// ---------------------------------------------------------------------------
// Launch
// ---------------------------------------------------------------------------
extern "C" void kernel_launch(void* const* d_in, const int* in_sizes, int n_in,
                              void* d_out, int out_size) {
    const float* x     = (const float*)d_in[0];
    const float* wq_s  = (const float*)d_in[1];
    const float* wk_s  = (const float*)d_in[2];
    const float* wv_s  = (const float*)d_in[3];
    const float* wo_s  = (const float*)d_in[4];
    const float* qn_w  = (const float*)d_in[5];
    const float* kn_w  = (const float*)d_in[6];
    const float* cosT  = (const float*)d_in[7];
    const float* sinT  = (const float*)d_in[8];
    const int*   wq    = (const int*)d_in[9];
    const int*   wk    = (const int*)d_in[10];
    const int*   wv    = (const int*)d_in[11];
    const int*   wo    = (const int*)d_in[12];
    const int*   lens  = (const int*)d_in[13];
    float*       out   = (float*)d_out;

    __half *pwq, *pwk, *pwv, *pwo, *pxh, *pattnh, *pvh;
    float *pq, *pk;
    cudaGetSymbolAddress((void**)&pwq, g_wq);
    cudaGetSymbolAddress((void**)&pwk, g_wk);
    cudaGetSymbolAddress((void**)&pwv, g_wv);
    cudaGetSymbolAddress((void**)&pwo, g_wo);
    cudaGetSymbolAddress((void**)&pxh, g_xh);
    cudaGetSymbolAddress((void**)&pattnh, g_attnh);
    cudaGetSymbolAddress((void**)&pvh, g_vh);
    cudaGetSymbolAddress((void**)&pq, g_q);
    cudaGetSymbolAddress((void**)&pk, g_k);

    cudaFuncSetAttribute(hgemm<float>,
                         cudaFuncAttributeMaxDynamicSharedMemorySize, HG_BYTES);
    cudaFuncSetAttribute(hgemm<__half>,
                         cudaFuncAttributeMaxDynamicSharedMemorySize, HG_BYTES);
    cudaFuncSetAttribute(flash_attn,
                         cudaFuncAttributeMaxDynamicSharedMemorySize, FA_BYTES);

    const int cblocks = (DD * DD) / (256 * 8);
    convert_w<<<cblocks, 256>>>(wq, wq_s, pwq);
    convert_w<<<cblocks, 256>>>(wk, wk_s, pwk);
    convert_w<<<cblocks, 256>>>(wv, wv_s, pwv);
    convert_w<<<cblocks, 256>>>(wo, wo_s, pwo);
    convert_x<<<(MM * DD) / (256 * 8), 256>>>(x, pxh);

    dim3 ggrid(16, 16);
    hgemm<float><<<ggrid, 256, HG_BYTES>>>(pxh, pwq, pq);
    hgemm<float><<<ggrid, 256, HG_BYTES>>>(pxh, pwk, pk);
    hgemm<__half><<<ggrid, 256, HG_BYTES>>>(pxh, pwv, pvh);

    norm_rope<<<dim3(MM, 2), 256>>>(cosT, sinT, qn_w, kn_w);

    flash_attn<<<dim3(SS / 64, HH, BB), 128, FA_BYTES>>>(lens);

    hgemm<float><<<ggrid, 256, HG_BYTES>>>(pattnh, pwo, out);
}

// round 6
// speedup vs baseline: 7.1427x; 1.0680x over previous
#include <cuda_runtime.h>
#include <cuda_fp16.h>
#include <cstdint>
#include <stdint.h>
#include <math.h>

using u32 = unsigned int;

// Problem constants
#define BB 2
#define SS 1024
#define DD 2048
#define HH 16
#define DHD 128
#define MM (BB * SS)   // 2048 rows

// ---------------------------------------------------------------------------
// Scratch (__device__ globals; allocation-free per harness rules)
// ---------------------------------------------------------------------------
__device__ __half g_wq[DD * DD];
__device__ __half g_wk[DD * DD];
__device__ __half g_wv[DD * DD];
__device__ __half g_wo[DD * DD];
__device__ __half g_xh[MM * DD];      // hidden_states fp16
__device__ __half g_attnh[MM * DD];   // attention output fp16
__device__ __half g_qh[MM * DD];      // Q (pre-norm, then post norm+rope in place)
__device__ __half g_kh[MM * DD];      // K (pre-norm, then post norm+rope in place)
__device__ __half g_vh[MM * DD];      // V (fp16)

// ---------------------------------------------------------------------------
// PTX helpers
// ---------------------------------------------------------------------------
__device__ __forceinline__ uint4 ldsm_x4(u32 addr) {
    uint4 r;
    asm volatile("ldmatrix.sync.aligned.m8n8.x4.shared.b16 {%0,%1,%2,%3}, [%4];"
                 : "=r"(r.x), "=r"(r.y), "=r"(r.z), "=r"(r.w) : "r"(addr));
    return r;
}
__device__ __forceinline__ uint4 ldsm_x4_t(u32 addr) {
    uint4 r;
    asm volatile("ldmatrix.sync.aligned.m8n8.x4.trans.shared.b16 {%0,%1,%2,%3}, [%4];"
                 : "=r"(r.x), "=r"(r.y), "=r"(r.z), "=r"(r.w) : "r"(addr));
    return r;
}
__device__ __forceinline__ void mma16816(float* c, const uint4& a, u32 b0, u32 b1) {
    asm volatile(
        "mma.sync.aligned.m16n8k16.row.col.f32.f16.f16.f32 "
        "{%0,%1,%2,%3}, {%4,%5,%6,%7}, {%8,%9}, {%0,%1,%2,%3};"
        : "+f"(c[0]), "+f"(c[1]), "+f"(c[2]), "+f"(c[3])
        : "r"(a.x), "r"(a.y), "r"(a.z), "r"(a.w), "r"(b0), "r"(b1));
}
__device__ __forceinline__ void cp16(u32 dst, const void* src) {
    asm volatile("cp.async.cg.shared.global [%0], [%1], 16;" :: "r"(dst), "l"(src));
}
#define CP_COMMIT() asm volatile("cp.async.commit_group;")
#define CP_WAIT(N)  asm volatile("cp.async.wait_group %0;" :: "n"(N))

__device__ __forceinline__ u32 h2u(float a, float b) {
    __half2 h = __floats2half2_rn(a, b);
    return *reinterpret_cast<u32*>(&h);
}
__device__ __forceinline__ u32 smaddr(const void* p) {
    return (u32)__cvta_generic_to_shared(p);
}

// ---------------------------------------------------------------------------
// Kernel 1: fused converts. grid.y: 0..3 -> weights (int8-in-int32 * scale),
// 4 -> hidden_states fp32->fp16.
// ---------------------------------------------------------------------------
__global__ __launch_bounds__(256) void convert_all(
    const int* __restrict__ wq, const int* __restrict__ wk,
    const int* __restrict__ wv, const int* __restrict__ wo,
    const float* __restrict__ wq_s, const float* __restrict__ wk_s,
    const float* __restrict__ wv_s, const float* __restrict__ wo_s,
    const float* __restrict__ x) {
    const int y = blockIdx.y;
    const int i = (blockIdx.x * 256 + threadIdx.x) * 8;
    __align__(16) __half h[8];
    if (y == 4) {
        float4 a = *(const float4*)(x + i);
        float4 b = *(const float4*)(x + i + 4);
        h[0] = __float2half(a.x); h[1] = __float2half(a.y);
        h[2] = __float2half(a.z); h[3] = __float2half(a.w);
        h[4] = __float2half(b.x); h[5] = __float2half(b.y);
        h[6] = __float2half(b.z); h[7] = __float2half(b.w);
        *(uint4*)(g_xh + i) = *(const uint4*)h;
        return;
    }
    const int*   w = (y == 0) ? wq : (y == 1) ? wk : (y == 2) ? wv : wo;
    const float* s = (y == 0) ? wq_s : (y == 1) ? wk_s : (y == 2) ? wv_s : wo_s;
    __half*    out = (y == 0) ? g_wq : (y == 1) ? g_wk : (y == 2) ? g_wv : g_wo;
    float sc = s[i >> 11];
    int4 a = *(const int4*)(w + i);
    int4 b = *(const int4*)(w + i + 4);
    h[0] = __float2half((float)a.x * sc);
    h[1] = __float2half((float)a.y * sc);
    h[2] = __float2half((float)a.z * sc);
    h[3] = __float2half((float)a.w * sc);
    h[4] = __float2half((float)b.x * sc);
    h[5] = __float2half((float)b.y * sc);
    h[6] = __float2half((float)b.z * sc);
    h[7] = __float2half((float)b.w * sc);
    *(uint4*)(out + i) = *(const uint4*)h;
}

// ---------------------------------------------------------------------------
// HGEMM core: 128x128 tile, BK=64, 3-stage cp.async, 256 thr, warp 64x32.
// ---------------------------------------------------------------------------
#define HG_STG 9216                       // halfs per matrix per stage (128*72)
#define HG_STAGE_BYTES (2 * HG_STG * 2)   // A+B, 36864 B
#define HG_BYTES (3 * HG_STAGE_BYTES)     // 110592 B

template <typename OutT>
__device__ __forceinline__ void store2(OutT* p, float a, float b);
template <> __device__ __forceinline__ void store2<float>(float* p, float a, float b) {
    *(float2*)p = make_float2(a, b);
}
template <> __device__ __forceinline__ void store2<__half>(__half* p, float a, float b) {
    *(__half2*)p = __floats2half2_rn(a, b);
}

template <typename OutT>
__device__ __forceinline__ void hgemm_body(const __half* __restrict__ A,
                                           const __half* __restrict__ B,
                                           OutT* __restrict__ C,
                                           __half* hsm, int bm, int bn) {
    const u32 smb = smaddr(hsm);
    const int t = threadIdx.x, warp = t >> 5, lane = t & 31;
    const int wm = (warp & 1) * 64, wn = (warp >> 1) * 32;
    const int lr = lane & 7, g = lane >> 3;
    const u32 aOff = (u32)(((wm + lr + (g & 1) * 8) * 72 + (g >> 1) * 8) * 2);
    const u32 bOff = (u32)(((wn + lr + (g >> 1) * 8) * 72 + (g & 1) * 8) * 2);

    float c[4][4][4];
#pragma unroll
    for (int mi = 0; mi < 4; mi++)
#pragma unroll
        for (int ni = 0; ni < 4; ni++)
#pragma unroll
            for (int e = 0; e < 4; e++) c[mi][ni][e] = 0.f;

    auto load_stage = [&](int st, int k0) {
        u32 sb = smb + (u32)(st * HG_STAGE_BYTES);
#pragma unroll
        for (int i = 0; i < 4; i++) {
            int id = t + 256 * i;
            int r = id >> 3, cc = id & 7;
            cp16(sb + (u32)((r * 72 + cc * 8) * 2),
                 A + (size_t)(bm + r) * DD + k0 + cc * 8);
            cp16(sb + (u32)(HG_STG * 2) + (u32)((r * 72 + cc * 8) * 2),
                 B + (size_t)(bn + r) * DD + k0 + cc * 8);
        }
    };

    load_stage(0, 0);  CP_COMMIT();
    load_stage(1, 64); CP_COMMIT();

    for (int kt = 0; kt < 32; kt++) {
        if (kt < 31) { CP_WAIT(1); } else { CP_WAIT(0); }
        __syncthreads();
        if (kt + 2 < 32) { load_stage((kt + 2) % 3, (kt + 2) * 64); CP_COMMIT(); }

        u32 ab = smb + (u32)((kt % 3) * HG_STAGE_BYTES) + aOff;
        u32 bb = smb + (u32)((kt % 3) * HG_STAGE_BYTES + HG_STG * 2) + bOff;
#pragma unroll
        for (int ks = 0; ks < 64; ks += 16) {
            uint4 af[4], bf[2];
#pragma unroll
            for (int mi = 0; mi < 4; mi++)
                af[mi] = ldsm_x4(ab + (u32)((mi * 16 * 72 + ks) * 2));
#pragma unroll
            for (int np = 0; np < 2; np++)
                bf[np] = ldsm_x4(bb + (u32)((np * 16 * 72 + ks) * 2));
#pragma unroll
            for (int mi = 0; mi < 4; mi++)
#pragma unroll
                for (int np = 0; np < 2; np++) {
                    mma16816(c[mi][np * 2 + 0], af[mi], bf[np].x, bf[np].y);
                    mma16816(c[mi][np * 2 + 1], af[mi], bf[np].z, bf[np].w);
                }
        }
    }

    const int r0 = bm + wm + (lane >> 2);
    const int cb = bn + wn + (lane & 3) * 2;
#pragma unroll
    for (int mi = 0; mi < 4; mi++)
#pragma unroll
        for (int ni = 0; ni < 4; ni++) {
            int row = r0 + mi * 16, col = cb + ni * 8;
            store2<OutT>(C + (size_t)row * DD + col, c[mi][ni][0], c[mi][ni][1]);
            store2<OutT>(C + (size_t)(row + 8) * DD + col, c[mi][ni][2], c[mi][ni][3]);
        }
}

// Kernel 2a: fused QKV GEMM (z selects weight + destination, all fp16 out)
__global__ __launch_bounds__(256, 2) void hgemm_qkv() {
    extern __shared__ __half hsm[];
    const int z = blockIdx.z;
    const __half* B = (z == 0) ? g_wq : (z == 1) ? g_wk : g_wv;
    __half*       C = (z == 0) ? g_qh : (z == 1) ? g_kh : g_vh;
    hgemm_body<__half>(g_xh, B, C, hsm, blockIdx.y * 128, blockIdx.x * 128);
}

// Kernel 2b: O-projection GEMM (fp32 out to harness buffer)
__global__ __launch_bounds__(256, 2) void hgemm_o(float* __restrict__ C) {
    extern __shared__ __half hsm[];
    hgemm_body<float>(g_attnh, g_wo, C, hsm, blockIdx.y * 128, blockIdx.x * 128);
}

// ---------------------------------------------------------------------------
// Kernel 3: RMSNorm + RoPE, fp16 in/out, in place on g_qh / g_kh.
// ---------------------------------------------------------------------------
__global__ __launch_bounds__(256) void norm_rope(const float* __restrict__ cosT,
                                                 const float* __restrict__ sinT,
                                                 const float* __restrict__ qn_w,
                                                 const float* __restrict__ kn_w) {
    __half* x       = (blockIdx.y == 0) ? g_qh : g_kh;
    const float* w  = (blockIdx.y == 0) ? qn_w : kn_w;
    const int row = blockIdx.x;
    const int s   = row & (SS - 1);
    const int t   = threadIdx.x;

    __shared__ float buf[DD];
    __shared__ float red[8];

    __half* xr = x + (size_t)row * DD;
    float ss = 0.f;
    {
        int i = t * 8;
        uint4 raw = *(const uint4*)(xr + i);
        const __half* hp = (const __half*)&raw;
#pragma unroll
        for (int j = 0; j < 8; j++) {
            float v = __half2float(hp[j]);
            buf[i + j] = v;
            ss += v * v;
        }
    }
#pragma unroll
    for (int off = 16; off; off >>= 1) ss += __shfl_xor_sync(0xffffffffu, ss, off);
    if ((t & 31) == 0) red[t >> 5] = ss;
    __syncthreads();
    float tot = 0.f;
#pragma unroll
    for (int wI = 0; wI < 8; wI++) tot += red[wI];
    const float inv = rsqrtf(tot * (1.0f / DD) + 1e-6f);

#pragma unroll
    for (int u = 0; u < 4; u++) {
        int p  = t + u * 256;
        int hh = p >> 6;
        int i  = p & 63;
        int d1 = hh * DHD + i;
        int d2 = d1 + 64;
        float y1 = buf[d1] * inv * w[d1];
        float y2 = buf[d2] * inv * w[d2];
        float c1 = cosT[s * DHD + i],      s1 = sinT[s * DHD + i];
        float c2 = cosT[s * DHD + 64 + i], s2 = sinT[s * DHD + 64 + i];
        xr[d1] = __float2half(y1 * c1 - y2 * s1);
        xr[d2] = __float2half(y2 * c2 + y1 * s2);
    }
}

// ---------------------------------------------------------------------------
// Kernel 4: flash-attention, mma.m16n8k16, 2-stage KV pipeline (80 KB smem
// -> 2 CTAs/SM). 128 threads, 64 q-rows per CTA.
// ---------------------------------------------------------------------------
#define FA_Q_HALFS (64 * 128)
#define FA_KV_HALFS (64 * 128)
#define FA_STAGE_HALFS (2 * FA_KV_HALFS)
#define FA_BYTES ((FA_Q_HALFS + 2 * FA_STAGE_HALFS) * 2)   // 81920

__device__ __forceinline__ void fa_load_kv(u32 smb, int st, const __half* kg,
                                           const __half* vg, int kt, int t) {
    u32 kb = smb + (u32)((FA_Q_HALFS + st * FA_STAGE_HALFS) * 2);
    u32 vb = kb + (u32)(FA_KV_HALFS * 2);
#pragma unroll
    for (int i = 0; i < 8; i++) {
        int id = t + 128 * i;
        int r = id >> 4, cc = id & 15;
        u32 off = (u32)(((r * 128) + ((cc ^ (r & 7)) << 3)) << 1);
        cp16(kb + off, kg + (size_t)(kt * 64 + r) * DD + cc * 8);
        cp16(vb + off, vg + (size_t)(kt * 64 + r) * DD + cc * 8);
    }
}

__global__ __launch_bounds__(128) void flash_attn(const int* __restrict__ lengths) {
    extern __shared__ __half fsm[];
    const u32 smb = smaddr(fsm);

    const int qt = blockIdx.x, h = blockIdx.y, b = blockIdx.z;
    const int t = threadIdx.x, warp = t >> 5, lane = t & 31;
    const int lr = lane & 7, g = lane >> 3;
    const int len = lengths[b];
    const int s0  = qt * 64;
    const int nkt = (len + 63) >> 6;

    const __half* qg = g_qh + (size_t)(b * SS) * DD + h * DHD;
    const __half* kg = g_kh + (size_t)(b * SS) * DD + h * DHD;
    const __half* vg = g_vh + (size_t)(b * SS) * DD + h * DHD;

#pragma unroll
    for (int i = 0; i < 8; i++) {
        int id = t + 128 * i;
        int r = id >> 4, cc = id & 15;
        u32 off = (u32)(((r * 128) + ((cc ^ (r & 7)) << 3)) << 1);
        cp16(smb + off, qg + (size_t)(s0 + r) * DD + cc * 8);
    }
    fa_load_kv(smb, 0, kg, vg, 0, t);
    CP_COMMIT();
    if (nkt > 1) { fa_load_kv(smb, 1, kg, vg, 1, t); CP_COMMIT(); }

    const int qrow = 16 * warp + lr + (g & 1) * 8, qx = qrow & 7;
    const int krow = lr + (g >> 1) * 8, kcol = g & 1, kx = krow & 7;
    const int vrow = lr + (g & 1) * 8, vcol = g >> 1, vx = vrow & 7;

    uint4 qf[8];
    float o[16][4];
#pragma unroll
    for (int j2 = 0; j2 < 16; j2++)
#pragma unroll
        for (int e = 0; e < 4; e++) o[j2][e] = 0.f;
    float m0 = -1e30f, m1 = -1e30f, l0 = 0.f, l1 = 0.f;
    const float scl = 0.08838834764831845f;   // 1/sqrt(128)

    for (int kt = 0; kt < nkt; kt++) {
        if (kt + 1 < nkt) { CP_WAIT(1); } else { CP_WAIT(0); }
        __syncthreads();
        if (kt == 0) {
#pragma unroll
            for (int ks = 0; ks < 8; ks++)
                qf[ks] = ldsm_x4(smb + (u32)(((qrow * 128) +
                                  (((2 * ks + (g >> 1)) ^ qx) << 3)) << 1));
        }

        const u32 kbase = smb + (u32)((FA_Q_HALFS + (kt & 1) * FA_STAGE_HALFS) * 2);
        const u32 vbase = kbase + (u32)(FA_KV_HALFS * 2);

        float s[8][4];
#pragma unroll
        for (int j = 0; j < 8; j++)
#pragma unroll
            for (int e = 0; e < 4; e++) s[j][e] = 0.f;

#pragma unroll
        for (int ks = 0; ks < 8; ks++) {
#pragma unroll
            for (int np = 0; np < 4; np++) {
                uint4 bf = ldsm_x4(kbase + (u32)((((16 * np + krow) * 128) +
                                    (((2 * ks + kcol) ^ kx) << 3)) << 1));
                mma16816(s[2 * np],     qf[ks], bf.x, bf.y);
                mma16816(s[2 * np + 1], qf[ks], bf.z, bf.w);
            }
        }

        const int cb = kt * 64 + 2 * (lane & 3);
        float mx0 = -1e30f, mx1 = -1e30f;
#pragma unroll
        for (int j = 0; j < 8; j++) {
            int c0 = cb + 8 * j;
            s[j][0] = (c0 < len)     ? s[j][0] * scl : -1e30f;
            s[j][1] = (c0 + 1 < len) ? s[j][1] * scl : -1e30f;
            s[j][2] = (c0 < len)     ? s[j][2] * scl : -1e30f;
            s[j][3] = (c0 + 1 < len) ? s[j][3] * scl : -1e30f;
            mx0 = fmaxf(mx0, fmaxf(s[j][0], s[j][1]));
            mx1 = fmaxf(mx1, fmaxf(s[j][2], s[j][3]));
        }
        mx0 = fmaxf(mx0, __shfl_xor_sync(0xffffffffu, mx0, 1));
        mx0 = fmaxf(mx0, __shfl_xor_sync(0xffffffffu, mx0, 2));
        mx1 = fmaxf(mx1, __shfl_xor_sync(0xffffffffu, mx1, 1));
        mx1 = fmaxf(mx1, __shfl_xor_sync(0xffffffffu, mx1, 2));

        float mn0 = fmaxf(m0, mx0), mn1 = fmaxf(m1, mx1);
        float al0 = __expf(m0 - mn0), al1 = __expf(m1 - mn1);
        float sum0 = 0.f, sum1 = 0.f;
        u32 pf[8][2];
#pragma unroll
        for (int j = 0; j < 8; j++) {
            float p0 = __expf(s[j][0] - mn0), p1 = __expf(s[j][1] - mn0);
            float p2 = __expf(s[j][2] - mn1), p3 = __expf(s[j][3] - mn1);
            sum0 += p0 + p1; sum1 += p2 + p3;
            pf[j][0] = h2u(p0, p1);
            pf[j][1] = h2u(p2, p3);
        }
        sum0 += __shfl_xor_sync(0xffffffffu, sum0, 1);
        sum0 += __shfl_xor_sync(0xffffffffu, sum0, 2);
        sum1 += __shfl_xor_sync(0xffffffffu, sum1, 1);
        sum1 += __shfl_xor_sync(0xffffffffu, sum1, 2);
        l0 = l0 * al0 + sum0; l1 = l1 * al1 + sum1;
        m0 = mn0; m1 = mn1;
#pragma unroll
        for (int j2 = 0; j2 < 16; j2++) {
            o[j2][0] *= al0; o[j2][1] *= al0;
            o[j2][2] *= al1; o[j2][3] *= al1;
        }

#pragma unroll
        for (int k2 = 0; k2 < 4; k2++) {
            uint4 a;
            a.x = pf[2 * k2][0];     a.y = pf[2 * k2][1];
            a.z = pf[2 * k2 + 1][0]; a.w = pf[2 * k2 + 1][1];
#pragma unroll
            for (int np = 0; np < 8; np++) {
                uint4 bf = ldsm_x4_t(vbase + (u32)((((16 * k2 + vrow) * 128) +
                                     (((2 * np + vcol) ^ vx) << 3)) << 1));
                mma16816(o[2 * np],     a, bf.x, bf.y);
                mma16816(o[2 * np + 1], a, bf.z, bf.w);
            }
        }

        __syncthreads();   // all reads of slot kt&1 done before overwrite
        if (kt + 2 < nkt) { fa_load_kv(smb, kt & 1, kg, vg, kt + 2, t); CP_COMMIT(); }
    }

    const float il0 = 1.f / l0, il1 = 1.f / l1;
    const int r0 = s0 + 16 * warp + (lane >> 2);
    __half* ob = g_attnh + (size_t)(b * SS) * DD + h * DHD;
#pragma unroll
    for (int j2 = 0; j2 < 16; j2++) {
        int col = 8 * j2 + 2 * (lane & 3);
        *(__half2*)(ob + (size_t)r0 * DD + col) =
            __floats2half2_rn(o[j2][0] * il0, o[j2][1] * il0);
        *(__half2*)(ob + (size_t)(r0 + 8) * DD + col) =
            __floats2half2_rn(o[j2][2] * il1, o[j2][3] * il1);
    }
}

// ---------------------------------------------------------------------------
// Launch
// ---------------------------------------------------------------------------
extern "C" void kernel_launch(void* const* d_in, const int* in_sizes, int n_in,
                              void* d_out, int out_size) {
    const float* x     = (const float*)d_in[0];
    const float* wq_s  = (const float*)d_in[1];
    const float* wk_s  = (const float*)d_in[2];
    const float* wv_s  = (const float*)d_in[3];
    const float* wo_s  = (const float*)d_in[4];
    const float* qn_w  = (const float*)d_in[5];
    const float* kn_w  = (const float*)d_in[6];
    const float* cosT  = (const float*)d_in[7];
    const float* sinT  = (const float*)d_in[8];
    const int*   wq    = (const int*)d_in[9];
    const int*   wk    = (const int*)d_in[10];
    const int*   wv    = (const int*)d_in[11];
    const int*   wo    = (const int*)d_in[12];
    const int*   lens  = (const int*)d_in[13];
    float*       out   = (float*)d_out;

    cudaFuncSetAttribute(hgemm_qkv,
                         cudaFuncAttributeMaxDynamicSharedMemorySize, HG_BYTES);
    cudaFuncSetAttribute(hgemm_o,
                         cudaFuncAttributeMaxDynamicSharedMemorySize, HG_BYTES);
    cudaFuncSetAttribute(flash_attn,
                         cudaFuncAttributeMaxDynamicSharedMemorySize, FA_BYTES);

    convert_all<<<dim3((DD * DD) / (256 * 8), 5), 256>>>(
        wq, wk, wv, wo, wq_s, wk_s, wv_s, wo_s, x);

    hgemm_qkv<<<dim3(16, 16, 3), 256, HG_BYTES>>>();

    norm_rope<<<dim3(MM, 2), 256>>>(cosT, sinT, qn_w, kn_w);

    flash_attn<<<dim3(SS / 64, HH, BB), 128, FA_BYTES>>>(lens);

    hgemm_o<<<dim3(16, 16), 256, HG_BYTES>>>(out);
}